// round 6
// baseline (speedup 1.0000x reference)
#include <cuda_runtime.h>

#define BB 256     // batch
#define TT 256     // time steps
#define DD 64      // input dim
#define HH 512     // hidden
#define OO 10      // output classes

#define NBLK 128   // rec grid: 4 bt x 2 jt x 16 sk (all co-resident, 1/SM)
#define NSK  16    // K-splits in recurrence
#define NPB  4     // partial ring buffers (skew bound is 2; 4 is safe margin)

// ---------------- scratch (static device globals; no allocation allowed) ----
__device__ float g_xp0[TT * BB * HH];        // [t][b][h]
__device__ float g_seq0[TT * BB * HH];       // [t][b][h]
__device__ float g_xp1[TT * BB * HH];        // [t][b][h]
__device__ float g_part[NPB][NSK][BB * HH];  // ring x split x [b][j]
__device__ float g_hlast[BB * HH];

// progress flags: g_flag[bt][jt][sk] = last step whose partials are published
__device__ __align__(128) int g_flag[4][2][NSK];

// ---------------- packed fp32x2 helpers -------------------------------------
__device__ __forceinline__ unsigned long long dup2(float a) {
    unsigned long long d;
    asm("mov.b64 %0, {%1, %1};" : "=l"(d) : "f"(a));
    return d;
}
__device__ __forceinline__ void fma2(unsigned long long& d,
                                     unsigned long long a, unsigned long long b) {
    asm("fma.rn.f32x2 %0, %1, %2, %0;" : "+l"(d) : "l"(a), "l"(b));
}
__device__ __forceinline__ void unpack2(unsigned long long d, float& lo, float& hi) {
    asm("mov.b64 {%0, %1}, %2;" : "=f"(lo), "=f"(hi) : "l"(d));
}

// ---------------- flag ops ---------------------------------------------------
__device__ __forceinline__ void post_flag(int* p, int t) {
    asm volatile("st.release.gpu.b32 [%0], %1;" :: "l"(p), "r"(t) : "memory");
}
// poll 16 contiguous flags until all >= need (thread 0 only)
__device__ __forceinline__ void poll_flags(const int* f, int need) {
    for (;;) {
        int ok = 1;
#pragma unroll
        for (int i = 0; i < 4; ++i) {
            int a, b, c, d;
            asm volatile("ld.volatile.v4.b32 {%0,%1,%2,%3}, [%4];"
                         : "=r"(a), "=r"(b), "=r"(c), "=r"(d)
                         : "l"(f + i * 4));
            ok &= (a >= need) & (b >= need) & (c >= need) & (d >= need);
        }
        if (ok) break;
    }
}

// ---------------- flag reset (launched before each rec instance) ------------
__global__ void reset_flags() {
    ((int*)g_flag)[threadIdx.x] = 0;    // 4*2*16 = 128 ints
}

// ---------------- GEMM: C[m][n] = sum_k A[m][k]*W[n][k] + b1[n] + b2[n] -----
// Tile 128m x 128n, BK=16, 256 threads, 8m x 8n micro (fp32x2, 1 B/MAC),
// double-buffered. Both smem tiles stored transposed [k][row].
__global__ __launch_bounds__(256, 2) void gemm_nt_bias(
    const float* __restrict__ A, const float* __restrict__ Wm,
    const float* __restrict__ b1, const float* __restrict__ b2,
    float* __restrict__ Cm, int M, int N, int K, int permute)
{
    __shared__ float sA[2][16 * 128];   // [k][m]
    __shared__ float sW[2][16 * 128];   // [k][n]

    int m0 = blockIdx.x * 128;
    int n0 = blockIdx.y * 128;
    int tid = threadIdx.x;

    const float* Ap[2];
    const float* Wp[2];
#pragma unroll
    for (int it = 0; it < 2; ++it) {
        int q = tid + it * 256;
        int row = q >> 2;
        int gm = m0 + row;
        if (permute) {
            int b_ = gm & (BB - 1);
            int t_ = gm >> 8;                  // BB == 256
            Ap[it] = A + ((size_t)b_ * TT + t_) * K;
        } else {
            Ap[it] = A + (size_t)gm * K;
        }
        Wp[it] = Wm + (size_t)(n0 + row) * K;
    }

    int tn = tid & 15;            // -> n = tn*8
    int tm = tid >> 4;            // -> m = tm*8

    unsigned long long acc[4][8]; // [m-pair][n]
#pragma unroll
    for (int i = 0; i < 4; ++i)
#pragma unroll
        for (int j = 0; j < 8; ++j) acc[i][j] = 0ull;

    // prologue: stage chunk 0
    float4 a4[2], w4[2];
#pragma unroll
    for (int it = 0; it < 2; ++it) {
        int q = tid + it * 256;
        int kq = q & 3;
        a4[it] = *(const float4*)(Ap[it] + kq * 4);
        w4[it] = *(const float4*)(Wp[it] + kq * 4);
    }
#pragma unroll
    for (int it = 0; it < 2; ++it) {
        int q = tid + it * 256;
        int row = q >> 2, kq = q & 3;
        float av[4] = {a4[it].x, a4[it].y, a4[it].z, a4[it].w};
        float wv[4] = {w4[it].x, w4[it].y, w4[it].z, w4[it].w};
#pragma unroll
        for (int l = 0; l < 4; ++l) {
            sA[0][(kq * 4 + l) * 128 + row] = av[l];
            sW[0][(kq * 4 + l) * 128 + row] = wv[l];
        }
    }
    __syncthreads();

    int cur = 0;
    for (int kt = 16; kt < K; kt += 16) {
#pragma unroll
        for (int it = 0; it < 2; ++it) {
            int q = tid + it * 256;
            int kq = q & 3;
            a4[it] = *(const float4*)(Ap[it] + kt + kq * 4);
            w4[it] = *(const float4*)(Wp[it] + kt + kq * 4);
        }
#pragma unroll
        for (int k = 0; k < 16; ++k) {
            ulonglong2 m01 = *(const ulonglong2*)&sA[cur][k * 128 + tm * 8];
            ulonglong2 m23 = *(const ulonglong2*)&sA[cur][k * 128 + tm * 8 + 4];
            float4 wA = *(const float4*)&sW[cur][k * 128 + tn * 8];
            float4 wB = *(const float4*)&sW[cur][k * 128 + tn * 8 + 4];
            unsigned long long wd[8];
            wd[0] = dup2(wA.x); wd[1] = dup2(wA.y);
            wd[2] = dup2(wA.z); wd[3] = dup2(wA.w);
            wd[4] = dup2(wB.x); wd[5] = dup2(wB.y);
            wd[6] = dup2(wB.z); wd[7] = dup2(wB.w);
            unsigned long long hp[4] = {m01.x, m01.y, m23.x, m23.y};
#pragma unroll
            for (int i = 0; i < 4; ++i)
#pragma unroll
                for (int j = 0; j < 8; ++j)
                    fma2(acc[i][j], hp[i], wd[j]);
        }
        int nxt = cur ^ 1;
#pragma unroll
        for (int it = 0; it < 2; ++it) {
            int q = tid + it * 256;
            int row = q >> 2, kq = q & 3;
            float av[4] = {a4[it].x, a4[it].y, a4[it].z, a4[it].w};
            float wv[4] = {w4[it].x, w4[it].y, w4[it].z, w4[it].w};
#pragma unroll
            for (int l = 0; l < 4; ++l) {
                sA[nxt][(kq * 4 + l) * 128 + row] = av[l];
                sW[nxt][(kq * 4 + l) * 128 + row] = wv[l];
            }
        }
        __syncthreads();
        cur = nxt;
    }
#pragma unroll
    for (int k = 0; k < 16; ++k) {
        ulonglong2 m01 = *(const ulonglong2*)&sA[cur][k * 128 + tm * 8];
        ulonglong2 m23 = *(const ulonglong2*)&sA[cur][k * 128 + tm * 8 + 4];
        float4 wA = *(const float4*)&sW[cur][k * 128 + tn * 8];
        float4 wB = *(const float4*)&sW[cur][k * 128 + tn * 8 + 4];
        unsigned long long wd[8];
        wd[0] = dup2(wA.x); wd[1] = dup2(wA.y);
        wd[2] = dup2(wA.z); wd[3] = dup2(wA.w);
        wd[4] = dup2(wB.x); wd[5] = dup2(wB.y);
        wd[6] = dup2(wB.z); wd[7] = dup2(wB.w);
        unsigned long long hp[4] = {m01.x, m01.y, m23.x, m23.y};
#pragma unroll
        for (int i = 0; i < 4; ++i)
#pragma unroll
            for (int j = 0; j < 8; ++j)
                fma2(acc[i][j], hp[i], wd[j]);
    }

    float bias[8];
#pragma unroll
    for (int j = 0; j < 8; ++j) {
        int n = n0 + tn * 8 + j;
        bias[j] = b1[n] + (b2 ? b2[n] : 0.f);
    }
#pragma unroll
    for (int i = 0; i < 4; ++i) {
        float r0[8], r1[8];
#pragma unroll
        for (int j = 0; j < 8; ++j) unpack2(acc[i][j], r0[j], r1[j]);
        int m = m0 + tm * 8 + i * 2;
        size_t off0 = (size_t)m * N + n0 + tn * 8;
        size_t off1 = off0 + N;
        float4 v;
        v.x = r0[0] + bias[0]; v.y = r0[1] + bias[1];
        v.z = r0[2] + bias[2]; v.w = r0[3] + bias[3];
        *(float4*)(Cm + off0) = v;
        v.x = r0[4] + bias[4]; v.y = r0[5] + bias[5];
        v.z = r0[6] + bias[6]; v.w = r0[7] + bias[7];
        *(float4*)(Cm + off0 + 4) = v;
        v.x = r1[0] + bias[0]; v.y = r1[1] + bias[1];
        v.z = r1[2] + bias[2]; v.w = r1[3] + bias[3];
        *(float4*)(Cm + off1) = v;
        v.x = r1[4] + bias[4]; v.y = r1[5] + bias[5];
        v.z = r1[6] + bias[6]; v.w = r1[7] + bias[7];
        *(float4*)(Cm + off1 + 4) = v;
    }
}

// ---------------- persistent recurrence kernel ------------------------------
// h_t = relu(xp[t-1] + h_{t-1} @ Whh^T).
// Grid 128 = 4 bt x 2 jt x 16 sk. CTA tile: 64b x 256j, K-slice of 32.
// Wait-free dataflow: producers publish per-step flags (st.release.gpu);
// a consumer polls only the 16 flags of its producer jt-half. 4-deep partial
// ring makes this WAR-safe (dependency skew bound = 2 steps).
__global__ __launch_bounds__(256, 1) void rec_kernel(
    const float* __restrict__ xp,      // [T][B][H]
    const float* __restrict__ Whh,     // [H][H]
    float* __restrict__ seq_out,       // [T][B][H] or nullptr
    float* __restrict__ h_last)        // [B][H]    or nullptr
{
    extern __shared__ float smem[];
    float* sW = smem;                  // [32 k][256 j]  32 KB
    float* sA = smem + 32 * 256;       // [32 k][64 b]    8 KB

    int cid = blockIdx.x;
    int bt = cid >> 5;                 // 0..3
    int jt = (cid >> 4) & 1;           // 0..1
    int sk = cid & 15;                 // 0..15
    int b0 = bt * 64, j0 = jt * 256, k0 = sk * 32;
    int jt_p = sk >> 3;                // jt-half that produces my k-slice

    int tid = threadIdx.x;

    int* myflag = &g_flag[bt][jt][sk];
    const int* depflags = &g_flag[bt][jt_p][0];

    // Load Whh slice transposed: sW[k][j] = Whh[j0+j][k0+k]
    for (int i = tid; i < 2048; i += 256) {
        int j  = i >> 3;               // 0..255
        int kq = i & 7;                // 0..7
        float4 w4 = *(const float4*)(Whh + (size_t)(j0 + j) * HH + k0 + kq * 4);
        sW[(kq * 4 + 0) * 256 + j] = w4.x;
        sW[(kq * 4 + 1) * 256 + j] = w4.y;
        sW[(kq * 4 + 2) * 256 + j] = w4.z;
        sW[(kq * 4 + 3) * 256 + j] = w4.w;
    }

    const int wr_seq = (seq_out != nullptr) && (jt == 0);

    // combine indices: thread -> (b = tid>>2, jj = (tid&3)*8)
    int cb  = tid >> 2;
    int cj  = (tid & 3) * 8;
    // micro indices: 8 tb-groups x 32 tj-groups
    int tb = tid >> 5;                 // -> b = tb*8
    int tj = tid & 31;                 // -> j = tj*8

    for (int t = 1; t < TT; ++t) {
        const float* xprev = xp + (size_t)(t - 1) * BB * HH;
        size_t rowoff = (size_t)(b0 + cb) * HH + k0 + cj;

        // xp prefetch — independent of flags, hides L2 latency under the wait
        float4 s0 = *(const float4*)(xprev + rowoff);
        float4 s1 = *(const float4*)(xprev + rowoff + 4);

        if (t > 1) {
            if (tid == 0) {
                poll_flags(depflags, t - 1);
                __threadfence();       // acquire
            }
            __syncthreads();
            const float* pbase = &g_part[(t - 1) & (NPB - 1)][0][0];
#pragma unroll
            for (int s2 = 0; s2 < NSK; ++s2) {
                const float* ps = pbase + (size_t)s2 * (BB * HH) + rowoff;
                float4 q0 = *(const float4*)(ps);
                float4 q1 = *(const float4*)(ps + 4);
                s0.x += q0.x; s0.y += q0.y; s0.z += q0.z; s0.w += q0.w;
                s1.x += q1.x; s1.y += q1.y; s1.z += q1.z; s1.w += q1.w;
            }
        }
        s0.x = fmaxf(s0.x, 0.f); s0.y = fmaxf(s0.y, 0.f);
        s0.z = fmaxf(s0.z, 0.f); s0.w = fmaxf(s0.w, 0.f);
        s1.x = fmaxf(s1.x, 0.f); s1.y = fmaxf(s1.y, 0.f);
        s1.z = fmaxf(s1.z, 0.f); s1.w = fmaxf(s1.w, 0.f);
        // transposed store: sA[jj][b]
        sA[(cj + 0) * 64 + cb] = s0.x;
        sA[(cj + 1) * 64 + cb] = s0.y;
        sA[(cj + 2) * 64 + cb] = s0.z;
        sA[(cj + 3) * 64 + cb] = s0.w;
        sA[(cj + 4) * 64 + cb] = s1.x;
        sA[(cj + 5) * 64 + cb] = s1.y;
        sA[(cj + 6) * 64 + cb] = s1.z;
        sA[(cj + 7) * 64 + cb] = s1.w;
        if (wr_seq) {
            float* so = seq_out + (size_t)(t - 1) * BB * HH + rowoff;
            *(float4*)(so)     = s0;
            *(float4*)(so + 4) = s1;
        }
        __syncthreads();

        // ---- MMA: acc[b 8][j 8] += sum_{k=0..31} h[k][b] * W[k][j] --------
        unsigned long long acc[4][8];
#pragma unroll
        for (int i = 0; i < 4; ++i)
#pragma unroll
            for (int j = 0; j < 8; ++j) acc[i][j] = 0ull;

#pragma unroll
        for (int k = 0; k < 32; ++k) {
            ulonglong2 h01 = *(const ulonglong2*)&sA[k * 64 + tb * 8];
            ulonglong2 h23 = *(const ulonglong2*)&sA[k * 64 + tb * 8 + 4];
            float4 wA = *(const float4*)&sW[k * 256 + tj * 8];
            float4 wB = *(const float4*)&sW[k * 256 + tj * 8 + 4];
            unsigned long long wd[8];
            wd[0] = dup2(wA.x); wd[1] = dup2(wA.y);
            wd[2] = dup2(wA.z); wd[3] = dup2(wA.w);
            wd[4] = dup2(wB.x); wd[5] = dup2(wB.y);
            wd[6] = dup2(wB.z); wd[7] = dup2(wB.w);
            unsigned long long hp[4] = {h01.x, h01.y, h23.x, h23.y};
#pragma unroll
            for (int i = 0; i < 4; ++i)
#pragma unroll
                for (int j = 0; j < 8; ++j)
                    fma2(acc[i][j], hp[i], wd[j]);
        }

        // ---- write partials into ring slot t ------------------------------
        float* pw = &g_part[t & (NPB - 1)][sk][0];
#pragma unroll
        for (int i = 0; i < 4; ++i) {
            float r0[8], r1[8];
#pragma unroll
            for (int j = 0; j < 8; ++j) unpack2(acc[i][j], r0[j], r1[j]);
            size_t off0 = (size_t)(b0 + tb * 8 + i * 2) * HH + j0 + tj * 8;
            size_t off1 = off0 + HH;
            float4 v;
            v.x = r0[0]; v.y = r0[1]; v.z = r0[2]; v.w = r0[3];
            *(float4*)(pw + off0) = v;
            v.x = r0[4]; v.y = r0[5]; v.z = r0[6]; v.w = r0[7];
            *(float4*)(pw + off0 + 4) = v;
            v.x = r1[0]; v.y = r1[1]; v.z = r1[2]; v.w = r1[3];
            *(float4*)(pw + off1) = v;
            v.x = r1[4]; v.y = r1[5]; v.z = r1[6]; v.w = r1[7];
            *(float4*)(pw + off1 + 4) = v;
        }
        __syncthreads();
        if (tid == 0) post_flag(myflag, t);   // release: publishes partials
    }

    // ---- final combine: h_T slice written by jt==0 CTAs --------------------
    if (jt == 0) {
        if (tid == 0) {
            poll_flags(depflags, TT - 1);
            __threadfence();
        }
        __syncthreads();
        const float* pbase = &g_part[(TT - 1) & (NPB - 1)][0][0];
        const float* xl = xp + (size_t)(TT - 1) * BB * HH;
        size_t rowoff = (size_t)(b0 + cb) * HH + k0 + cj;
        float4 s0 = *(const float4*)(xl + rowoff);
        float4 s1 = *(const float4*)(xl + rowoff + 4);
#pragma unroll
        for (int s2 = 0; s2 < NSK; ++s2) {
            const float* ps = pbase + (size_t)s2 * (BB * HH) + rowoff;
            float4 q0 = *(const float4*)(ps);
            float4 q1 = *(const float4*)(ps + 4);
            s0.x += q0.x; s0.y += q0.y; s0.z += q0.z; s0.w += q0.w;
            s1.x += q1.x; s1.y += q1.y; s1.z += q1.z; s1.w += q1.w;
        }
        s0.x = fmaxf(s0.x, 0.f); s0.y = fmaxf(s0.y, 0.f);
        s0.z = fmaxf(s0.z, 0.f); s0.w = fmaxf(s0.w, 0.f);
        s1.x = fmaxf(s1.x, 0.f); s1.y = fmaxf(s1.y, 0.f);
        s1.z = fmaxf(s1.z, 0.f); s1.w = fmaxf(s1.w, 0.f);
        if (seq_out) {
            float* so = seq_out + (size_t)(TT - 1) * BB * HH + rowoff;
            *(float4*)(so)     = s0;
            *(float4*)(so + 4) = s1;
        }
        if (h_last) {
            *(float4*)(h_last + rowoff)     = s0;
            *(float4*)(h_last + rowoff + 4) = s1;
        }
    }
}

// ---------------- head: relu(h @ fc1^T + b1) @ fc2^T + b2 -------------------
__global__ __launch_bounds__(256) void head_kernel(
    const float* __restrict__ hl, const float* __restrict__ w1,
    const float* __restrict__ b1f, const float* __restrict__ w2,
    const float* __restrict__ b2f, float* __restrict__ out)
{
    __shared__ float sh[8];
    int b = blockIdx.x;
    int tid = threadIdx.x;
    int w = tid >> 5;
    int lane = tid & 31;

    const float* hb = hl + (size_t)b * HH;
    const float* wr = w1 + (size_t)w * HH;
    float ssum = 0.f;
    for (int k = lane; k < HH; k += 32) ssum += hb[k] * wr[k];
#pragma unroll
    for (int o = 16; o; o >>= 1) ssum += __shfl_xor_sync(0xffffffffu, ssum, o);
    if (lane == 0) sh[w] = fmaxf(ssum + b1f[w], 0.f);
    __syncthreads();
    if (tid < OO) {
        float r = b2f[tid];
#pragma unroll
        for (int j = 0; j < 8; ++j) r += sh[j] * w2[tid * 8 + j];
        out[(size_t)b * OO + tid] = r;
    }
}

// ---------------- launch ----------------------------------------------------
extern "C" void kernel_launch(void* const* d_in, const int* in_sizes, int n_in,
                              void* d_out, int out_size)
{
    const float* x     = (const float*)d_in[0];
    const float* w_ih0 = (const float*)d_in[1];
    const float* w_hh0 = (const float*)d_in[2];
    const float* b_ih0 = (const float*)d_in[3];
    const float* b_hh0 = (const float*)d_in[4];
    const float* w_ih1 = (const float*)d_in[5];
    const float* w_hh1 = (const float*)d_in[6];
    const float* b_ih1 = (const float*)d_in[7];
    const float* b_hh1 = (const float*)d_in[8];
    const float* fc1_w = (const float*)d_in[9];
    const float* fc1_b = (const float*)d_in[10];
    const float* fc2_w = (const float*)d_in[11];
    const float* fc2_b = (const float*)d_in[12];
    float* out = (float*)d_out;

    void* p;
    cudaGetSymbolAddress(&p, g_xp0);   float* xp0   = (float*)p;
    cudaGetSymbolAddress(&p, g_seq0);  float* seq0  = (float*)p;
    cudaGetSymbolAddress(&p, g_xp1);   float* xp1   = (float*)p;
    cudaGetSymbolAddress(&p, g_hlast); float* hlast = (float*)p;

    size_t rec_smem = (size_t)(32 * 256 + 32 * 64) * sizeof(float);  // 40960 B
    cudaFuncSetAttribute(rec_kernel,
                         cudaFuncAttributeMaxDynamicSharedMemorySize,
                         (int)rec_smem);

    dim3 gg(TT * BB / 128, HH / 128);   // 512 x 4

    // layer-0 input projection (rows permuted from x[b][t][d])
    gemm_nt_bias<<<gg, 256>>>(x, w_ih0, b_ih0, b_hh0, xp0,
                              TT * BB, HH, DD, 1);
    // layer-0 recurrence (writes seq0)
    reset_flags<<<1, 128>>>();
    rec_kernel<<<NBLK, 256, rec_smem>>>(xp0, w_hh0, seq0, nullptr);
    // layer-1 input projection
    gemm_nt_bias<<<gg, 256>>>(seq0, w_ih1, b_ih1, b_hh1, xp1,
                              TT * BB, HH, HH, 0);
    // layer-1 recurrence (only final hidden state needed)
    reset_flags<<<1, 128>>>();
    rec_kernel<<<NBLK, 256, rec_smem>>>(xp1, w_hh1, nullptr, hlast);
    // head
    head_kernel<<<BB, 256>>>(hlast, fc1_w, fc1_b, fc2_w, fc2_b, out);
}

// round 8
// speedup vs baseline: 1.6675x; 1.6675x over previous
#include <cuda_runtime.h>
#include <cuda_bf16.h>
#include <cstdint>

#define BB 256     // batch
#define TT 256     // time steps
#define DD 64      // input dim
#define HH 512     // hidden
#define OO 10      // output classes

#define NBLK 128   // rec grid: 4 bt x 2 jt x 16 sk (all co-resident, 1/SM)
#define GRP  32    // CTAs per bt dependency group
#define NSK  16    // K-splits in recurrence

// ---------------- scratch (static device globals; no allocation allowed) ----
__device__ float g_xp0[TT * BB * HH];        // [t][b][h]
__device__ float g_seq0[TT * BB * HH];       // [t][b][h]
__device__ float g_xp1[TT * BB * HH];        // [t][b][h]
__device__ float g_part[2][NSK][BB * HH];    // ping-pong x split x [b][j]
__device__ float g_hlast[BB * HH];

__device__ unsigned g_gcnt[4];               // per-bt arrival counters
__device__ unsigned g_ggen[4];               // per-bt generation

// bf16 split weights for the HMMA input projections
__device__ __nv_bfloat16 g_w0h[HH * DD], g_w0l[HH * DD];
__device__ __nv_bfloat16 g_w1h[HH * HH], g_w1l[HH * HH];

// ---------------- packed fp32x2 helpers (rec kernel) ------------------------
__device__ __forceinline__ unsigned long long dup2(float a) {
    unsigned long long d;
    asm("mov.b64 %0, {%1, %1};" : "=l"(d) : "f"(a));
    return d;
}
__device__ __forceinline__ void fma2(unsigned long long& d,
                                     unsigned long long a, unsigned long long b) {
    asm("fma.rn.f32x2 %0, %1, %2, %0;" : "+l"(d) : "l"(a), "l"(b));
}
__device__ __forceinline__ void unpack2(unsigned long long d, float& lo, float& hi) {
    asm("mov.b64 {%0, %1}, %2;" : "=f"(lo), "=f"(hi) : "l"(d));
}

// ---------------- per-group sense barrier (32 CTAs sharing bt) --------------
__device__ __forceinline__ void grp_bar(int bt) {
    __syncthreads();
    if (threadIdx.x == 0) {
        __threadfence();   // release
        unsigned snap = *(volatile unsigned*)&g_ggen[bt];
        unsigned old = atomicAdd(&g_gcnt[bt], 1u);
        if (old == GRP - 1u) {
            g_gcnt[bt] = 0u;
            __threadfence();
            atomicExch(&g_ggen[bt], snap + 1u);
        } else {
            while (*(volatile unsigned*)&g_ggen[bt] == snap) {}
            __threadfence();  // acquire
        }
    }
    __syncthreads();
}

// ---------------- HMMA plumbing ---------------------------------------------
__device__ __forceinline__ uint32_t s2u(const void* p) {
    uint32_t a;
    asm("{ .reg .u64 t; cvta.to.shared.u64 t, %1; cvt.u32.u64 %0, t; }"
        : "=r"(a) : "l"(p));
    return a;
}
__device__ __forceinline__ void ldm_x4(uint32_t& r0, uint32_t& r1,
                                       uint32_t& r2, uint32_t& r3,
                                       uint32_t addr) {
    asm volatile("ldmatrix.sync.aligned.m8n8.x4.shared.b16 {%0,%1,%2,%3}, [%4];"
                 : "=r"(r0), "=r"(r1), "=r"(r2), "=r"(r3) : "r"(addr));
}
__device__ __forceinline__ void ldm_x2(uint32_t& r0, uint32_t& r1,
                                       uint32_t addr) {
    asm volatile("ldmatrix.sync.aligned.m8n8.x2.shared.b16 {%0,%1}, [%2];"
                 : "=r"(r0), "=r"(r1) : "r"(addr));
}
__device__ __forceinline__ void mma_bf16(float* d, const uint32_t* a,
                                         uint32_t b0, uint32_t b1) {
    asm volatile(
        "mma.sync.aligned.m16n8k16.row.col.f32.bf16.bf16.f32 "
        "{%0,%1,%2,%3}, {%4,%5,%6,%7}, {%8,%9}, {%0,%1,%2,%3};"
        : "+f"(d[0]), "+f"(d[1]), "+f"(d[2]), "+f"(d[3])
        : "r"(a[0]), "r"(a[1]), "r"(a[2]), "r"(a[3]), "r"(b0), "r"(b1));
}

// ---------------- weight convert: fp32 -> bf16 hi/lo ------------------------
__global__ void convert_w(const float* __restrict__ w0,
                          const float* __restrict__ w1) {
    int i = blockIdx.x * 256 + threadIdx.x;
    if (i < HH * DD) {
        float v = w0[i];
        __nv_bfloat16 h = __float2bfloat16(v);
        g_w0h[i] = h;
        g_w0l[i] = __float2bfloat16(v - __bfloat162float(h));
    }
    if (i < HH * HH) {
        float v = w1[i];
        __nv_bfloat16 h = __float2bfloat16(v);
        g_w1h[i] = h;
        g_w1l[i] = __float2bfloat16(v - __bfloat162float(h));
    }
}

// ---------------- HMMA GEMM: C = A @ W^T + b1 + b2 --------------------------
// Split bf16: C = Ah*Wh + Ah*Wl + Al*Wh, fp32 accum (err ~2^-18).
// Tile 128m x 128n, BK=32, 256 threads (8 warps = 4m x 2n), warp 32m x 64n.
// SMEM in 8x8-block layout (block = 8 rows x 16B) -> conflict-free ldmatrix.
#define HM_AH 0
#define HM_AL 8192
#define HM_WH 16384
#define HM_WL 24576
#define HM_SB 32768          // staged bias: 128 floats
#define HM_TOTAL (32768 + 512)

__global__ __launch_bounds__(256, 2) void gemm_hmma(
    const float* __restrict__ A,
    const __nv_bfloat16* __restrict__ Wh, const __nv_bfloat16* __restrict__ Wl,
    const float* __restrict__ b1, const float* __restrict__ b2,
    float* __restrict__ Cm, int K, int permute)
{
    __shared__ __align__(128) uint8_t sm[HM_TOTAL];
    uint32_t sbase = s2u(sm);

    int tid = threadIdx.x;
    int lane = tid & 31;
    int wid = tid >> 5;
    int wm = wid & 3;          // warp m index (0..3), 32 rows each
    int wn = wid >> 2;         // warp n index (0..1), 64 cols each
    int m0 = blockIdx.x * 128;
    int n0 = blockIdx.y * 128;

    if (tid < 128) {
        int n = n0 + tid;
        ((float*)(sm + HM_SB))[tid] = b1[n] + (b2 ? b2[n] : 0.f);
    }

    // A row pointers for staging (4 tasks/thread; task idx: row=idx>>3, kq=idx&7)
    const float* Ap[4];
#pragma unroll
    for (int it = 0; it < 4; ++it) {
        int idx = tid + it * 256;
        int row = idx >> 3;
        int gm = m0 + row;
        if (permute) {
            int b_ = gm & (BB - 1);
            int t_ = gm >> 8;                  // BB == 256
            Ap[it] = A + ((size_t)b_ * TT + t_) * K;
        } else {
            Ap[it] = A + (size_t)gm * K;
        }
    }

    float acc[2][8][4];
#pragma unroll
    for (int mf = 0; mf < 2; ++mf)
#pragma unroll
        for (int nf = 0; nf < 8; ++nf)
#pragma unroll
            for (int q = 0; q < 4; ++q) acc[mf][nf][q] = 0.f;

    int sub = lane >> 3;       // 0..3
    int r8  = lane & 7;

    int nch = K >> 5;
    for (int c = 0; c < nch; ++c) {
        int kc = c << 5;
        __syncthreads();       // previous-iter reads (and bias write) complete

        // ---- stage A: fp32 -> bf16 hi/lo into block layout ---------------
#pragma unroll
        for (int it = 0; it < 4; ++it) {
            int idx = tid + it * 256;
            int row = idx >> 3, kq = idx & 7;
            float4 v = *(const float4*)(Ap[it] + kc + kq * 4);
            __nv_bfloat16 h0 = __float2bfloat16(v.x);
            __nv_bfloat16 h1 = __float2bfloat16(v.y);
            __nv_bfloat16 h2 = __float2bfloat16(v.z);
            __nv_bfloat16 h3 = __float2bfloat16(v.w);
            __nv_bfloat16 l0 = __float2bfloat16(v.x - __bfloat162float(h0));
            __nv_bfloat16 l1 = __float2bfloat16(v.y - __bfloat162float(h1));
            __nv_bfloat16 l2 = __float2bfloat16(v.z - __bfloat162float(h2));
            __nv_bfloat16 l3 = __float2bfloat16(v.w - __bfloat162float(h3));
            uint2 hp, lp;
            hp.x = (uint32_t)__bfloat16_as_ushort(h0) |
                   ((uint32_t)__bfloat16_as_ushort(h1) << 16);
            hp.y = (uint32_t)__bfloat16_as_ushort(h2) |
                   ((uint32_t)__bfloat16_as_ushort(h3) << 16);
            lp.x = (uint32_t)__bfloat16_as_ushort(l0) |
                   ((uint32_t)__bfloat16_as_ushort(l1) << 16);
            lp.y = (uint32_t)__bfloat16_as_ushort(l2) |
                   ((uint32_t)__bfloat16_as_ushort(l3) << 16);
            int kt = kq >> 1, kcol = (kq & 1) * 4;
            uint32_t off = (uint32_t)(((kt * 16) + (row >> 3)) * 128 +
                                      (row & 7) * 16 + kcol * 2);
            *(uint2*)(sm + HM_AH + off) = hp;
            *(uint2*)(sm + HM_AL + off) = lp;
        }
        // ---- stage W: bf16 hi/lo (pre-split) into block layout -----------
#pragma unroll
        for (int it = 0; it < 4; ++it) {
            int idx = tid + it * 256;
            int row = idx >> 3, kq = idx & 7;
            size_t go = (size_t)(n0 + row) * K + kc + kq * 4;
            uint2 hv = *(const uint2*)(Wh + go);
            uint2 lv = *(const uint2*)(Wl + go);
            int kt = kq >> 1, kcol = (kq & 1) * 4;
            uint32_t off = (uint32_t)(((kt * 16) + (row >> 3)) * 128 +
                                      (row & 7) * 16 + kcol * 2);
            *(uint2*)(sm + HM_WH + off) = hv;
            *(uint2*)(sm + HM_WL + off) = lv;
        }
        __syncthreads();

        // ---- compute: 2 k16 steps, 3 split passes ------------------------
#pragma unroll
        for (int s = 0; s < 2; ++s) {
            uint32_t ah[2][4], al[2][4];
#pragma unroll
            for (int mf = 0; mf < 2; ++mf) {
                int mt = wm * 4 + mf * 2 + (sub & 1);
                int kt = s * 2 + (sub >> 1);
                uint32_t ad = sbase + HM_AH +
                              (uint32_t)(((kt * 16) + mt) * 128 + r8 * 16);
                ldm_x4(ah[mf][0], ah[mf][1], ah[mf][2], ah[mf][3], ad);
                ldm_x4(al[mf][0], al[mf][1], al[mf][2], al[mf][3],
                       ad + (HM_AL - HM_AH));
            }
#pragma unroll
            for (int nf = 0; nf < 8; ++nf) {
                int nt = wn * 8 + nf;
                int ktb = s * 2 + (sub & 1);
                uint32_t bd = sbase + HM_WH +
                              (uint32_t)(((ktb * 16) + nt) * 128 + r8 * 16);
                uint32_t bh0, bh1, bl0, bl1;
                ldm_x2(bh0, bh1, bd);
                ldm_x2(bl0, bl1, bd + (HM_WL - HM_WH));
                mma_bf16(acc[0][nf], ah[0], bh0, bh1);
                mma_bf16(acc[1][nf], ah[1], bh0, bh1);
                mma_bf16(acc[0][nf], ah[0], bl0, bl1);
                mma_bf16(acc[1][nf], ah[1], bl0, bl1);
                mma_bf16(acc[0][nf], al[0], bh0, bh1);
                mma_bf16(acc[1][nf], al[1], bh0, bh1);
            }
        }
    }

    // ---- epilogue: D frag thread map: rows g=lane>>2 (+8), cols (lane&3)*2
    const float* sb = (const float*)(sm + HM_SB);
#pragma unroll
    for (int mf = 0; mf < 2; ++mf) {
        int mrow = m0 + wm * 32 + mf * 16 + (lane >> 2);
#pragma unroll
        for (int nf = 0; nf < 8; ++nf) {
            int ncol = wn * 64 + nf * 8 + (lane & 3) * 2;
            float bb0 = sb[ncol], bb1 = sb[ncol + 1];
            float2 v0, v1;
            v0.x = acc[mf][nf][0] + bb0; v0.y = acc[mf][nf][1] + bb1;
            v1.x = acc[mf][nf][2] + bb0; v1.y = acc[mf][nf][3] + bb1;
            *(float2*)(Cm + (size_t)mrow * HH + n0 + ncol) = v0;
            *(float2*)(Cm + (size_t)(mrow + 8) * HH + n0 + ncol) = v1;
        }
    }
}

// ---------------- persistent recurrence kernel (R5 config, unchanged) -------
__global__ __launch_bounds__(256, 1) void rec_kernel(
    const float* __restrict__ xp,      // [T][B][H]
    const float* __restrict__ Whh,     // [H][H]
    float* __restrict__ seq_out,       // [T][B][H] or nullptr
    float* __restrict__ h_last)        // [B][H]    or nullptr
{
    extern __shared__ float smem[];
    float* sW = smem;                  // [32 k][256 j]  32 KB
    float* sA = smem + 32 * 256;       // [32 k][64 b]    8 KB

    int cid = blockIdx.x;
    int bt = cid >> 5;
    int jt = (cid >> 4) & 1;
    int sk = cid & 15;
    int b0 = bt * 64, j0 = jt * 256, k0 = sk * 32;

    int tid = threadIdx.x;

    for (int i = tid; i < 2048; i += 256) {
        int j  = i >> 3;
        int kq = i & 7;
        float4 w4 = *(const float4*)(Whh + (size_t)(j0 + j) * HH + k0 + kq * 4);
        sW[(kq * 4 + 0) * 256 + j] = w4.x;
        sW[(kq * 4 + 1) * 256 + j] = w4.y;
        sW[(kq * 4 + 2) * 256 + j] = w4.z;
        sW[(kq * 4 + 3) * 256 + j] = w4.w;
    }

    for (int i = tid; i < 4096; i += 256) {
        int b  = i >> 6;
        int jq = i & 63;
        *(float4*)&g_part[0][sk][(size_t)(b0 + b) * HH + j0 + jq * 4] =
            make_float4(0.f, 0.f, 0.f, 0.f);
    }
    grp_bar(bt);

    const int wr_seq = (seq_out != nullptr) && (jt == 0);

    int cb  = tid >> 2;
    int cj  = (tid & 3) * 8;
    int tb = tid >> 5;
    int tj = tid & 31;

    for (int t = 1; t < TT; ++t) {
        const float* pbase = &g_part[(t - 1) & 1][0][0];
        const float* xprev = xp + (size_t)(t - 1) * BB * HH;
        float* pw = &g_part[t & 1][sk][0];

        {
            size_t rowoff = (size_t)(b0 + cb) * HH + k0 + cj;
            float4 s0 = *(const float4*)(xprev + rowoff);
            float4 s1 = *(const float4*)(xprev + rowoff + 4);
#pragma unroll
            for (int s2 = 0; s2 < NSK; ++s2) {
                const float* ps = pbase + (size_t)s2 * (BB * HH) + rowoff;
                float4 q0 = *(const float4*)(ps);
                float4 q1 = *(const float4*)(ps + 4);
                s0.x += q0.x; s0.y += q0.y; s0.z += q0.z; s0.w += q0.w;
                s1.x += q1.x; s1.y += q1.y; s1.z += q1.z; s1.w += q1.w;
            }
            s0.x = fmaxf(s0.x, 0.f); s0.y = fmaxf(s0.y, 0.f);
            s0.z = fmaxf(s0.z, 0.f); s0.w = fmaxf(s0.w, 0.f);
            s1.x = fmaxf(s1.x, 0.f); s1.y = fmaxf(s1.y, 0.f);
            s1.z = fmaxf(s1.z, 0.f); s1.w = fmaxf(s1.w, 0.f);
            sA[(cj + 0) * 64 + cb] = s0.x;
            sA[(cj + 1) * 64 + cb] = s0.y;
            sA[(cj + 2) * 64 + cb] = s0.z;
            sA[(cj + 3) * 64 + cb] = s0.w;
            sA[(cj + 4) * 64 + cb] = s1.x;
            sA[(cj + 5) * 64 + cb] = s1.y;
            sA[(cj + 6) * 64 + cb] = s1.z;
            sA[(cj + 7) * 64 + cb] = s1.w;
            if (wr_seq) {
                float* so = seq_out + (size_t)(t - 1) * BB * HH + rowoff;
                *(float4*)(so)     = s0;
                *(float4*)(so + 4) = s1;
            }
        }
        __syncthreads();

        unsigned long long acc[4][8];
#pragma unroll
        for (int i = 0; i < 4; ++i)
#pragma unroll
            for (int j = 0; j < 8; ++j) acc[i][j] = 0ull;

#pragma unroll
        for (int k = 0; k < 32; ++k) {
            ulonglong2 h01 = *(const ulonglong2*)&sA[k * 64 + tb * 8];
            ulonglong2 h23 = *(const ulonglong2*)&sA[k * 64 + tb * 8 + 4];
            float4 wA = *(const float4*)&sW[k * 256 + tj * 8];
            float4 wB = *(const float4*)&sW[k * 256 + tj * 8 + 4];
            unsigned long long wd[8];
            wd[0] = dup2(wA.x); wd[1] = dup2(wA.y);
            wd[2] = dup2(wA.z); wd[3] = dup2(wA.w);
            wd[4] = dup2(wB.x); wd[5] = dup2(wB.y);
            wd[6] = dup2(wB.z); wd[7] = dup2(wB.w);
            unsigned long long hp[4] = {h01.x, h01.y, h23.x, h23.y};
#pragma unroll
            for (int i = 0; i < 4; ++i)
#pragma unroll
                for (int j = 0; j < 8; ++j)
                    fma2(acc[i][j], hp[i], wd[j]);
        }

#pragma unroll
        for (int i = 0; i < 4; ++i) {
            float r0[8], r1[8];
#pragma unroll
            for (int j = 0; j < 8; ++j) unpack2(acc[i][j], r0[j], r1[j]);
            size_t off0 = (size_t)(b0 + tb * 8 + i * 2) * HH + j0 + tj * 8;
            size_t off1 = off0 + HH;
            float4 v;
            v.x = r0[0]; v.y = r0[1]; v.z = r0[2]; v.w = r0[3];
            *(float4*)(pw + off0) = v;
            v.x = r0[4]; v.y = r0[5]; v.z = r0[6]; v.w = r0[7];
            *(float4*)(pw + off0 + 4) = v;
            v.x = r1[0]; v.y = r1[1]; v.z = r1[2]; v.w = r1[3];
            *(float4*)(pw + off1) = v;
            v.x = r1[4]; v.y = r1[5]; v.z = r1[6]; v.w = r1[7];
            *(float4*)(pw + off1 + 4) = v;
        }
        grp_bar(bt);
    }

    if (jt == 0) {
        const float* pbase = &g_part[(TT - 1) & 1][0][0];
        const float* xl = xp + (size_t)(TT - 1) * BB * HH;
        size_t rowoff = (size_t)(b0 + cb) * HH + k0 + cj;
        float4 s0 = *(const float4*)(xl + rowoff);
        float4 s1 = *(const float4*)(xl + rowoff + 4);
#pragma unroll
        for (int s2 = 0; s2 < NSK; ++s2) {
            const float* ps = pbase + (size_t)s2 * (BB * HH) + rowoff;
            float4 q0 = *(const float4*)(ps);
            float4 q1 = *(const float4*)(ps + 4);
            s0.x += q0.x; s0.y += q0.y; s0.z += q0.z; s0.w += q0.w;
            s1.x += q1.x; s1.y += q1.y; s1.z += q1.z; s1.w += q1.w;
        }
        s0.x = fmaxf(s0.x, 0.f); s0.y = fmaxf(s0.y, 0.f);
        s0.z = fmaxf(s0.z, 0.f); s0.w = fmaxf(s0.w, 0.f);
        s1.x = fmaxf(s1.x, 0.f); s1.y = fmaxf(s1.y, 0.f);
        s1.z = fmaxf(s1.z, 0.f); s1.w = fmaxf(s1.w, 0.f);
        if (seq_out) {
            float* so = seq_out + (size_t)(TT - 1) * BB * HH + rowoff;
            *(float4*)(so)     = s0;
            *(float4*)(so + 4) = s1;
        }
        if (h_last) {
            *(float4*)(h_last + rowoff)     = s0;
            *(float4*)(h_last + rowoff + 4) = s1;
        }
    }
}

// ---------------- head: relu(h @ fc1^T + b1) @ fc2^T + b2 -------------------
__global__ __launch_bounds__(256) void head_kernel(
    const float* __restrict__ hl, const float* __restrict__ w1,
    const float* __restrict__ b1f, const float* __restrict__ w2,
    const float* __restrict__ b2f, float* __restrict__ out)
{
    __shared__ float sh[8];
    int b = blockIdx.x;
    int tid = threadIdx.x;
    int w = tid >> 5;
    int lane = tid & 31;

    const float* hb = hl + (size_t)b * HH;
    const float* wr = w1 + (size_t)w * HH;
    float ssum = 0.f;
    for (int k = lane; k < HH; k += 32) ssum += hb[k] * wr[k];
#pragma unroll
    for (int o = 16; o; o >>= 1) ssum += __shfl_xor_sync(0xffffffffu, ssum, o);
    if (lane == 0) sh[w] = fmaxf(ssum + b1f[w], 0.f);
    __syncthreads();
    if (tid < OO) {
        float r = b2f[tid];
#pragma unroll
        for (int j = 0; j < 8; ++j) r += sh[j] * w2[tid * 8 + j];
        out[(size_t)b * OO + tid] = r;
    }
}

// ---------------- launch ----------------------------------------------------
extern "C" void kernel_launch(void* const* d_in, const int* in_sizes, int n_in,
                              void* d_out, int out_size)
{
    const float* x     = (const float*)d_in[0];
    const float* w_ih0 = (const float*)d_in[1];
    const float* w_hh0 = (const float*)d_in[2];
    const float* b_ih0 = (const float*)d_in[3];
    const float* b_hh0 = (const float*)d_in[4];
    const float* w_ih1 = (const float*)d_in[5];
    const float* w_hh1 = (const float*)d_in[6];
    const float* b_ih1 = (const float*)d_in[7];
    const float* b_hh1 = (const float*)d_in[8];
    const float* fc1_w = (const float*)d_in[9];
    const float* fc1_b = (const float*)d_in[10];
    const float* fc2_w = (const float*)d_in[11];
    const float* fc2_b = (const float*)d_in[12];
    float* out = (float*)d_out;

    void* p;
    cudaGetSymbolAddress(&p, g_xp0);   float* xp0   = (float*)p;
    cudaGetSymbolAddress(&p, g_seq0);  float* seq0  = (float*)p;
    cudaGetSymbolAddress(&p, g_xp1);   float* xp1   = (float*)p;
    cudaGetSymbolAddress(&p, g_hlast); float* hlast = (float*)p;
    cudaGetSymbolAddress(&p, g_w0h);   __nv_bfloat16* w0h = (__nv_bfloat16*)p;
    cudaGetSymbolAddress(&p, g_w0l);   __nv_bfloat16* w0l = (__nv_bfloat16*)p;
    cudaGetSymbolAddress(&p, g_w1h);   __nv_bfloat16* w1h = (__nv_bfloat16*)p;
    cudaGetSymbolAddress(&p, g_w1l);   __nv_bfloat16* w1l = (__nv_bfloat16*)p;

    size_t rec_smem = (size_t)(32 * 256 + 32 * 64) * sizeof(float);  // 40960 B
    cudaFuncSetAttribute(rec_kernel,
                         cudaFuncAttributeMaxDynamicSharedMemorySize,
                         (int)rec_smem);

    dim3 gg(TT * BB / 128, HH / 128);   // 512 x 4

    // split weights for HMMA projections
    convert_w<<<(HH * HH + 255) / 256, 256>>>(w_ih0, w_ih1);
    // layer-0 input projection (HMMA; rows permuted from x[b][t][d])
    gemm_hmma<<<gg, 256>>>(x, w0h, w0l, b_ih0, b_hh0, xp0, DD, 1);
    // layer-0 recurrence (writes seq0)
    rec_kernel<<<NBLK, 256, rec_smem>>>(xp0, w_hh0, seq0, nullptr);
    // layer-1 input projection (HMMA)
    gemm_hmma<<<gg, 256>>>(seq0, w1h, w1l, b_ih1, b_hh1, xp1, HH, 0);
    // layer-1 recurrence (only final hidden state needed)
    rec_kernel<<<NBLK, 256, rec_smem>>>(xp1, w_hh1, nullptr, hlast);
    // head
    head_kernel<<<BB, 256>>>(hlast, fc1_w, fc1_b, fc2_w, fc2_b, out);
}

// round 9
// speedup vs baseline: 2.6128x; 1.5669x over previous
#include <cuda_runtime.h>
#include <cuda_bf16.h>
#include <cstdint>

#define BB 256     // batch
#define TT 256     // time steps
#define DD 64      // input dim
#define HH 512     // hidden
#define OO 10      // output classes

#define NBLK 128   // rec grid: 8 bt x 16 jt (all co-resident, 1/SM)
#define GRP  16    // CTAs per bt dependency group

// ---------------- scratch (static device globals; no allocation allowed) ----
__device__ float    g_xp0[TT * BB * HH];     // [t][b][h] fp32
__device__ float    g_xp1[TT * BB * HH];     // [t][b][h] fp32
__device__ uint32_t g_seqp[TT * BB * HH];    // layer-0 h_t packed hi|lo bf16
__device__ uint32_t g_hpk[2][BB * HH];       // layer-1 h ping-pong packed
__device__ float    g_hlast[BB * HH];

__device__ unsigned g_gcnt[8];               // per-bt arrival counters
__device__ unsigned g_ggen[8];               // per-bt generation (monotonic)

// bf16 split weights for the HMMA input projections
__device__ __nv_bfloat16 g_w0h[HH * DD], g_w0l[HH * DD];
__device__ __nv_bfloat16 g_w1h[HH * HH], g_w1l[HH * HH];

// ---------------- per-group sense barrier (16 CTAs sharing bt) --------------
__device__ __forceinline__ void grp_bar(int bt) {
    __syncthreads();
    if (threadIdx.x == 0) {
        __threadfence();   // release
        unsigned snap = *(volatile unsigned*)&g_ggen[bt];
        unsigned old = atomicAdd(&g_gcnt[bt], 1u);
        if (old == GRP - 1u) {
            g_gcnt[bt] = 0u;
            __threadfence();
            atomicExch(&g_ggen[bt], snap + 1u);
        } else {
            while (*(volatile unsigned*)&g_ggen[bt] == snap) {}
            __threadfence();  // acquire
        }
    }
    __syncthreads();
}

// ---------------- HMMA plumbing ---------------------------------------------
__device__ __forceinline__ uint32_t s2u(const void* p) {
    uint32_t a;
    asm("{ .reg .u64 t; cvta.to.shared.u64 t, %1; cvt.u32.u64 %0, t; }"
        : "=r"(a) : "l"(p));
    return a;
}
__device__ __forceinline__ void ldm_x4(uint32_t& r0, uint32_t& r1,
                                       uint32_t& r2, uint32_t& r3,
                                       uint32_t addr) {
    asm volatile("ldmatrix.sync.aligned.m8n8.x4.shared.b16 {%0,%1,%2,%3}, [%4];"
                 : "=r"(r0), "=r"(r1), "=r"(r2), "=r"(r3) : "r"(addr));
}
__device__ __forceinline__ void ldm_x2(uint32_t& r0, uint32_t& r1,
                                       uint32_t addr) {
    asm volatile("ldmatrix.sync.aligned.m8n8.x2.shared.b16 {%0,%1}, [%2];"
                 : "=r"(r0), "=r"(r1) : "r"(addr));
}
__device__ __forceinline__ void mma_bf16(float* d, const uint32_t* a,
                                         uint32_t b0, uint32_t b1) {
    asm volatile(
        "mma.sync.aligned.m16n8k16.row.col.f32.bf16.bf16.f32 "
        "{%0,%1,%2,%3}, {%4,%5,%6,%7}, {%8,%9}, {%0,%1,%2,%3};"
        : "+f"(d[0]), "+f"(d[1]), "+f"(d[2]), "+f"(d[3])
        : "r"(a[0]), "r"(a[1]), "r"(a[2]), "r"(a[3]), "r"(b0), "r"(b1));
}
__device__ __forceinline__ uint32_t packsplit(float v) {
    __nv_bfloat16 h = __float2bfloat16(v);
    __nv_bfloat16 l = __float2bfloat16(v - __bfloat162float(h));
    return (uint32_t)__bfloat16_as_ushort(h) |
           ((uint32_t)__bfloat16_as_ushort(l) << 16);
}

// ---------------- weight convert: fp32 -> bf16 hi/lo ------------------------
__global__ void convert_w(const float* __restrict__ w0,
                          const float* __restrict__ w1) {
    int i = blockIdx.x * 256 + threadIdx.x;
    if (i < HH * DD) {
        float v = w0[i];
        __nv_bfloat16 h = __float2bfloat16(v);
        g_w0h[i] = h;
        g_w0l[i] = __float2bfloat16(v - __bfloat162float(h));
    }
    if (i < HH * HH) {
        float v = w1[i];
        __nv_bfloat16 h = __float2bfloat16(v);
        g_w1h[i] = h;
        g_w1l[i] = __float2bfloat16(v - __bfloat162float(h));
    }
}

// ---------------- HMMA GEMM: C = A @ W^T + b1 + b2 --------------------------
// Split bf16: C = Ah*Wh + Ah*Wl + Al*Wh, fp32 accum.
// Tile 128m x 128n, BK=32, 256 threads (8 warps = 4m x 2n), warp 32m x 64n.
// packed=1: A rows are uint32 (hi|lo<<16) pre-split bf16 pairs.
#define HM_AH 0
#define HM_AL 8192
#define HM_WH 16384
#define HM_WL 24576
#define HM_SB 32768          // staged bias: 128 floats
#define HM_TOTAL (32768 + 512)

__global__ __launch_bounds__(256, 2) void gemm_hmma(
    const float* __restrict__ A,
    const __nv_bfloat16* __restrict__ Wh, const __nv_bfloat16* __restrict__ Wl,
    const float* __restrict__ b1, const float* __restrict__ b2,
    float* __restrict__ Cm, int K, int permute, int packed)
{
    __shared__ __align__(128) uint8_t sm[HM_TOTAL];
    uint32_t sbase = s2u(sm);

    int tid = threadIdx.x;
    int lane = tid & 31;
    int wid = tid >> 5;
    int wm = wid & 3;          // warp m index (0..3), 32 rows each
    int wn = wid >> 2;         // warp n index (0..1), 64 cols each
    int m0 = blockIdx.x * 128;
    int n0 = blockIdx.y * 128;

    if (tid < 128) {
        int n = n0 + tid;
        ((float*)(sm + HM_SB))[tid] = b1[n] + (b2 ? b2[n] : 0.f);
    }

    const float* Ap[4];
#pragma unroll
    for (int it = 0; it < 4; ++it) {
        int idx = tid + it * 256;
        int row = idx >> 3;
        int gm = m0 + row;
        if (permute) {
            int b_ = gm & (BB - 1);
            int t_ = gm >> 8;                  // BB == 256
            Ap[it] = A + ((size_t)b_ * TT + t_) * K;
        } else {
            Ap[it] = A + (size_t)gm * K;
        }
    }

    float acc[2][8][4];
#pragma unroll
    for (int mf = 0; mf < 2; ++mf)
#pragma unroll
        for (int nf = 0; nf < 8; ++nf)
#pragma unroll
            for (int q = 0; q < 4; ++q) acc[mf][nf][q] = 0.f;

    int sub = lane >> 3;
    int r8  = lane & 7;

    int nch = K >> 5;
    for (int c = 0; c < nch; ++c) {
        int kc = c << 5;
        __syncthreads();

        // ---- stage A into block layout ------------------------------------
#pragma unroll
        for (int it = 0; it < 4; ++it) {
            int idx = tid + it * 256;
            int row = idx >> 3, kq = idx & 7;
            uint2 hp, lp;
            if (packed) {
                uint4 p = *(const uint4*)((const uint32_t*)Ap[it] + kc + kq * 4);
                hp.x = (p.x & 0xffffu) | (p.y << 16);
                hp.y = (p.z & 0xffffu) | (p.w << 16);
                lp.x = (p.x >> 16) | (p.y & 0xffff0000u);
                lp.y = (p.z >> 16) | (p.w & 0xffff0000u);
            } else {
                float4 v = *(const float4*)(Ap[it] + kc + kq * 4);
                uint32_t s0 = packsplit(v.x), s1 = packsplit(v.y);
                uint32_t s2 = packsplit(v.z), s3 = packsplit(v.w);
                hp.x = (s0 & 0xffffu) | (s1 << 16);
                hp.y = (s2 & 0xffffu) | (s3 << 16);
                lp.x = (s0 >> 16) | (s1 & 0xffff0000u);
                lp.y = (s2 >> 16) | (s3 & 0xffff0000u);
            }
            int kt = kq >> 1, kcol = (kq & 1) * 4;
            uint32_t off = (uint32_t)(((kt * 16) + (row >> 3)) * 128 +
                                      (row & 7) * 16 + kcol * 2);
            *(uint2*)(sm + HM_AH + off) = hp;
            *(uint2*)(sm + HM_AL + off) = lp;
        }
        // ---- stage W (pre-split) ------------------------------------------
#pragma unroll
        for (int it = 0; it < 4; ++it) {
            int idx = tid + it * 256;
            int row = idx >> 3, kq = idx & 7;
            size_t go = (size_t)(n0 + row) * K + kc + kq * 4;
            uint2 hv = *(const uint2*)(Wh + go);
            uint2 lv = *(const uint2*)(Wl + go);
            int kt = kq >> 1, kcol = (kq & 1) * 4;
            uint32_t off = (uint32_t)(((kt * 16) + (row >> 3)) * 128 +
                                      (row & 7) * 16 + kcol * 2);
            *(uint2*)(sm + HM_WH + off) = hv;
            *(uint2*)(sm + HM_WL + off) = lv;
        }
        __syncthreads();

        // ---- compute: 2 k16 steps, 3 split passes -------------------------
#pragma unroll
        for (int s = 0; s < 2; ++s) {
            uint32_t ah[2][4], al[2][4];
#pragma unroll
            for (int mf = 0; mf < 2; ++mf) {
                int mt = wm * 4 + mf * 2 + (sub & 1);
                int kt = s * 2 + (sub >> 1);
                uint32_t ad = sbase + HM_AH +
                              (uint32_t)(((kt * 16) + mt) * 128 + r8 * 16);
                ldm_x4(ah[mf][0], ah[mf][1], ah[mf][2], ah[mf][3], ad);
                ldm_x4(al[mf][0], al[mf][1], al[mf][2], al[mf][3],
                       ad + (HM_AL - HM_AH));
            }
#pragma unroll
            for (int nf = 0; nf < 8; ++nf) {
                int nt = wn * 8 + nf;
                int ktb = s * 2 + (sub & 1);
                uint32_t bd = sbase + HM_WH +
                              (uint32_t)(((ktb * 16) + nt) * 128 + r8 * 16);
                uint32_t bh0, bh1, bl0, bl1;
                ldm_x2(bh0, bh1, bd);
                ldm_x2(bl0, bl1, bd + (HM_WL - HM_WH));
                mma_bf16(acc[0][nf], ah[0], bh0, bh1);
                mma_bf16(acc[1][nf], ah[1], bh0, bh1);
                mma_bf16(acc[0][nf], ah[0], bl0, bl1);
                mma_bf16(acc[1][nf], ah[1], bl0, bl1);
                mma_bf16(acc[0][nf], al[0], bh0, bh1);
                mma_bf16(acc[1][nf], al[1], bh0, bh1);
            }
        }
    }

    const float* sb = (const float*)(sm + HM_SB);
#pragma unroll
    for (int mf = 0; mf < 2; ++mf) {
        int mrow = m0 + wm * 32 + mf * 16 + (lane >> 2);
#pragma unroll
        for (int nf = 0; nf < 8; ++nf) {
            int ncol = wn * 64 + nf * 8 + (lane & 3) * 2;
            float bb0 = sb[ncol], bb1 = sb[ncol + 1];
            float2 v0, v1;
            v0.x = acc[mf][nf][0] + bb0; v0.y = acc[mf][nf][1] + bb1;
            v1.x = acc[mf][nf][2] + bb0; v1.y = acc[mf][nf][3] + bb1;
            *(float2*)(Cm + (size_t)mrow * HH + n0 + ncol) = v0;
            *(float2*)(Cm + (size_t)(mrow + 8) * HH + n0 + ncol) = v1;
        }
    }
}

// ---------------- persistent HMMA recurrence kernel -------------------------
// h_t = relu(xp[t] + h_{t-1} @ Whh^T), h_0 relu(xp[0]).
// Grid 128 = 8 bt x 16 jt. CTA tile: 32b x 32j, FULL K=512 (no split-K,
// no partial combine). h exchanged as packed hi|lo bf16 uint32.
// Whh hi/lo persists in SMEM (block layout, XOR-swizzled); h staged per step.
// 8 warps: warp = (mt = wid&1 -> 16 b-rows, jb = wid>>1 -> 8 j-cols).
// 3-pass split HMMA, fp32 accumulators.
#define RS_WH 0
#define RS_WL 32768
#define RS_AH 65536
#define RS_AL 98304
#define RS_TOTAL 131072

__global__ __launch_bounds__(256, 1) void rec_kernel(
    const float* __restrict__ xp,      // [T][B][H]
    const float* __restrict__ Whh,     // [H][H] fp32
    uint32_t* __restrict__ hist,       // packed h ring: [(mask+1)][B][H]
    int hmask,                         // 255 (full seq) or 1 (ping-pong)
    float* __restrict__ h_last)        // [B][H] fp32 or nullptr
{
    extern __shared__ uint8_t sm[];
    uint32_t sb = s2u(sm);

    int cid = blockIdx.x;
    int bt = cid >> 4;                 // 0..7
    int jt = cid & 15;                 // 0..15
    int b0 = bt * 32, j0 = jt * 32;

    int tid = threadIdx.x;
    int lane = tid & 31, wid = tid >> 5;
    int sub = lane >> 3, r8 = lane & 7;
    int mt = wid & 1;                  // 16-row m-tile
    int jb = wid >> 1;                 // 8-col j-block

    // ---- preload Whh slice (32 j-rows x 512 k) as hi/lo, swizzled blocks --
    for (int idx = tid; idx < 4096; idx += 256) {
        int row = idx >> 7, kq = idx & 127;          // kq: 4-elem group
        float4 v = *(const float4*)(Whh + (size_t)(j0 + row) * HH + kq * 4);
        uint32_t s0 = packsplit(v.x), s1 = packsplit(v.y);
        uint32_t s2 = packsplit(v.z), s3 = packsplit(v.w);
        uint2 hi, lo;
        hi.x = (s0 & 0xffffu) | (s1 << 16);
        hi.y = (s2 & 0xffffu) | (s3 << 16);
        lo.x = (s0 >> 16) | (s1 & 0xffff0000u);
        lo.y = (s2 >> 16) | (s3 & 0xffff0000u);
        int kb = kq >> 1;
        uint32_t off = (uint32_t)kb * 512u + (uint32_t)(row >> 3) * 128u +
                       ((uint32_t)((row & 7) ^ (kb & 7)) << 4) +
                       (uint32_t)(kq & 1) * 8u;
        *(uint2*)(sm + RS_WH + off) = hi;
        *(uint2*)(sm + RS_WL + off) = lo;
    }

    // output fragment coordinates (m16n8 D layout)
    int brow = b0 + mt * 16 + (lane >> 2);
    int jcol = j0 + jb * 8 + (lane & 3) * 2;

    for (int t = 0; t < TT; ++t) {
        float acc[4] = {0.f, 0.f, 0.f, 0.f};

        if (t > 0) {
            // ---- stage h_{t-1}: 32 rows x 512 k, packed -> AH/AL ---------
            const uint32_t* hsrc = hist + (size_t)((t - 1) & hmask) * BB * HH;
#pragma unroll
            for (int it = 0; it < 16; ++it) {
                int idx = tid + it * 256;
                int row = idx >> 7, kq = idx & 127;
                uint4 p = *(const uint4*)(hsrc + (size_t)(b0 + row) * HH + kq * 4);
                uint2 hi, lo;
                hi.x = (p.x & 0xffffu) | (p.y << 16);
                hi.y = (p.z & 0xffffu) | (p.w << 16);
                lo.x = (p.x >> 16) | (p.y & 0xffff0000u);
                lo.y = (p.z >> 16) | (p.w & 0xffff0000u);
                int kb = kq >> 1;
                uint32_t off = (uint32_t)kb * 512u +
                               (uint32_t)(row >> 3) * 128u +
                               ((uint32_t)((row & 7) ^ (kb & 7)) << 4) +
                               (uint32_t)(kq & 1) * 8u;
                *(uint2*)(sm + RS_AH + off) = hi;
                *(uint2*)(sm + RS_AL + off) = lo;
            }
            __syncthreads();

            // ---- 3-pass HMMA over K=512 (32 k16 tiles) -------------------
#pragma unroll 4
            for (int ks = 0; ks < 32; ++ks) {
                int kbA = ks * 2 + (sub >> 1);
                uint32_t aoff = (uint32_t)kbA * 512u +
                                (uint32_t)(mt * 2 + (sub & 1)) * 128u +
                                ((uint32_t)(r8 ^ (kbA & 7)) << 4);
                uint32_t ah[4], al[4];
                ldm_x4(ah[0], ah[1], ah[2], ah[3], sb + RS_AH + aoff);
                ldm_x4(al[0], al[1], al[2], al[3], sb + RS_AL + aoff);

                int kbB = ks * 2 + (sub & 1);
                uint32_t boff = (uint32_t)kbB * 512u + (uint32_t)jb * 128u +
                                ((uint32_t)(r8 ^ (kbB & 7)) << 4);
                uint32_t bh0, bh1, bl0, bl1;
                ldm_x2(bh0, bh1, sb + RS_WH + boff);
                ldm_x2(bl0, bl1, sb + RS_WL + boff);

                mma_bf16(acc, ah, bh0, bh1);
                mma_bf16(acc, ah, bl0, bl1);
                mma_bf16(acc, al, bh0, bh1);
            }
        }

        // ---- output: v = relu(acc + xp[t]); publish packed ---------------
        const float* xpt = xp + (size_t)t * BB * HH;
        float2 x0 = *(const float2*)(xpt + (size_t)brow * HH + jcol);
        float2 x1 = *(const float2*)(xpt + (size_t)(brow + 8) * HH + jcol);
        float v0 = fmaxf(acc[0] + x0.x, 0.f);
        float v1 = fmaxf(acc[1] + x0.y, 0.f);
        float v2 = fmaxf(acc[2] + x1.x, 0.f);
        float v3 = fmaxf(acc[3] + x1.y, 0.f);

        uint32_t* hdst = hist + (size_t)(t & hmask) * BB * HH;
        uint2 pa, pb;
        pa.x = packsplit(v0); pa.y = packsplit(v1);
        pb.x = packsplit(v2); pb.y = packsplit(v3);
        *(uint2*)(hdst + (size_t)brow * HH + jcol) = pa;
        *(uint2*)(hdst + (size_t)(brow + 8) * HH + jcol) = pb;

        if (h_last && t == TT - 1) {
            *(float2*)(h_last + (size_t)brow * HH + jcol) =
                make_float2(v0, v1);
            *(float2*)(h_last + (size_t)(brow + 8) * HH + jcol) =
                make_float2(v2, v3);
        }
        grp_bar(bt);   // h_t published group-wide; also fences smem reuse
    }
}

// ---------------- head: relu(h @ fc1^T + b1) @ fc2^T + b2 -------------------
__global__ __launch_bounds__(256) void head_kernel(
    const float* __restrict__ hl, const float* __restrict__ w1,
    const float* __restrict__ b1f, const float* __restrict__ w2,
    const float* __restrict__ b2f, float* __restrict__ out)
{
    __shared__ float sh[8];
    int b = blockIdx.x;
    int tid = threadIdx.x;
    int w = tid >> 5;
    int lane = tid & 31;

    const float* hb = hl + (size_t)b * HH;
    const float* wr = w1 + (size_t)w * HH;
    float ssum = 0.f;
    for (int k = lane; k < HH; k += 32) ssum += hb[k] * wr[k];
#pragma unroll
    for (int o = 16; o; o >>= 1) ssum += __shfl_xor_sync(0xffffffffu, ssum, o);
    if (lane == 0) sh[w] = fmaxf(ssum + b1f[w], 0.f);
    __syncthreads();
    if (tid < OO) {
        float r = b2f[tid];
#pragma unroll
        for (int j = 0; j < 8; ++j) r += sh[j] * w2[tid * 8 + j];
        out[(size_t)b * OO + tid] = r;
    }
}

// ---------------- launch ----------------------------------------------------
extern "C" void kernel_launch(void* const* d_in, const int* in_sizes, int n_in,
                              void* d_out, int out_size)
{
    const float* x     = (const float*)d_in[0];
    const float* w_ih0 = (const float*)d_in[1];
    const float* w_hh0 = (const float*)d_in[2];
    const float* b_ih0 = (const float*)d_in[3];
    const float* b_hh0 = (const float*)d_in[4];
    const float* w_ih1 = (const float*)d_in[5];
    const float* w_hh1 = (const float*)d_in[6];
    const float* b_ih1 = (const float*)d_in[7];
    const float* b_hh1 = (const float*)d_in[8];
    const float* fc1_w = (const float*)d_in[9];
    const float* fc1_b = (const float*)d_in[10];
    const float* fc2_w = (const float*)d_in[11];
    const float* fc2_b = (const float*)d_in[12];
    float* out = (float*)d_out;

    void* p;
    cudaGetSymbolAddress(&p, g_xp0);   float* xp0 = (float*)p;
    cudaGetSymbolAddress(&p, g_xp1);   float* xp1 = (float*)p;
    cudaGetSymbolAddress(&p, g_seqp);  uint32_t* seqp = (uint32_t*)p;
    cudaGetSymbolAddress(&p, g_hpk);   uint32_t* hpk = (uint32_t*)p;
    cudaGetSymbolAddress(&p, g_hlast); float* hlast = (float*)p;
    cudaGetSymbolAddress(&p, g_w0h);   __nv_bfloat16* w0h = (__nv_bfloat16*)p;
    cudaGetSymbolAddress(&p, g_w0l);   __nv_bfloat16* w0l = (__nv_bfloat16*)p;
    cudaGetSymbolAddress(&p, g_w1h);   __nv_bfloat16* w1h = (__nv_bfloat16*)p;
    cudaGetSymbolAddress(&p, g_w1l);   __nv_bfloat16* w1l = (__nv_bfloat16*)p;

    cudaFuncSetAttribute(rec_kernel,
                         cudaFuncAttributeMaxDynamicSharedMemorySize,
                         RS_TOTAL);

    dim3 gg(TT * BB / 128, HH / 128);   // 512 x 4

    // split weights for HMMA projections
    convert_w<<<(HH * HH + 255) / 256, 256>>>(w_ih0, w_ih1);
    // layer-0 input projection (HMMA; rows permuted from x[b][t][d])
    gemm_hmma<<<gg, 256>>>(x, w0h, w0l, b_ih0, b_hh0, xp0, DD, 1, 0);
    // layer-0 recurrence: HMMA, writes packed seq (mask 255 = full history)
    rec_kernel<<<NBLK, 256, RS_TOTAL>>>(xp0, w_hh0, seqp, TT - 1, nullptr);
    // layer-1 input projection (HMMA, packed-A from seqp)
    gemm_hmma<<<gg, 256>>>((const float*)seqp, w1h, w1l, b_ih1, b_hh1, xp1,
                           HH, 0, 1);
    // layer-1 recurrence: ping-pong packed h, emits fp32 h_last
    rec_kernel<<<NBLK, 256, RS_TOTAL>>>(xp1, w_hh1, hpk, 1, hlast);
    // head
    head_kernel<<<BB, 256>>>(hlast, fc1_w, fc1_b, fc2_w, fc2_b, out);
}